// round 4
// baseline (speedup 1.0000x reference)
#include <cuda_runtime.h>
#include <cuda_bf16.h>

// Quantum circuit: N_QUBITS=10 (N=1024 amplitudes), N_LAYERS=5.
// out[b,c,:] = U @ state[b,c,:], state real input.
// Direct state-vector simulation per (b,c); state in shared memory; CNOT
// permutations (compile-time wiring) folded into GF(2) masks -> zero data
// motion; only 50 butterfly passes over smem.
//
// ENDIANNESS: JAX flattens (2,)*10 axes C-order, so qubit q (axis q+1) is bit
// (NQ-1-q) of the flattened index. All wiring below maps q -> bit NQ-1-q.

#define NQ      10
#define NST     1024
#define NLAYERS 5
#define NGATES  (NLAYERS * NQ)
#define NSTATES 2048          // 128 * 16
#define BLOCK   256

struct Plan {
    unsigned short m[NGATES];   // pair mask in array space  (phi^-1 e_b)
    unsigned short s[NGATES];   // parity mask               (row b of phi)
    unsigned char  hb[NGATES];  // highest set bit of m
    unsigned short outcols[NQ]; // columns of final phi^-1 -> output gather
};

constexpr int highest_bit(unsigned v) { int h = 0; while (v >>= 1) h++; return h; }

// Vector-application order (reverse of U's build order):
//   for l = L-1..0: CNOTs q=9..0 (control q -> target (q+1)%10), then u3^T q=9..0.
// Invariant: A[p] = v[phi(p)]. CNOT X gives phi' = X*phi (rows) and
// phi'^-1 = phi^-1*X (cols). Butterfly on logical bit b uses
// m = phi^-1 e_b (pair) and s = row_b(phi) (role parity).
constexpr Plan make_plan() {
    Plan P{};
    unsigned rows[NQ] = {};
    unsigned cols[NQ] = {};
    for (int r = 0; r < NQ; r++) { rows[r] = 1u << r; cols[r] = 1u << r; }
    int g = 0;
    for (int l = NLAYERS - 1; l >= 0; l--) {
        for (int q = NQ - 1; q >= 0; q--) {
            int c = NQ - 1 - q;                 // control bit
            int t = NQ - 1 - ((q + 1) % NQ);    // target bit
            rows[t] ^= rows[c];                 // phi <- X * phi
            cols[c] ^= cols[t];                 // phi^-1 <- phi^-1 * X
        }
        for (int q = NQ - 1; q >= 0; q--) {
            int b = NQ - 1 - q;                 // logical bit of qubit q
            P.m[g]  = (unsigned short)cols[b];
            P.s[g]  = (unsigned short)rows[b];
            P.hb[g] = (unsigned char)highest_bit(cols[b]);
            g++;
        }
    }
    for (int b = 0; b < NQ; b++) P.outcols[b] = (unsigned short)cols[b];
    return P;
}

static constexpr Plan PLAN = make_plan();

__device__ float2 g_gates[NGATES][4];   // scratch (no allocation)

// Coefficients for applying G^T to the vector:
//   n0 =  cos(th/2)*a0          + e^{i ph} sin(th/2)*a1
//   n1 = -e^{i lm} sin(th/2)*a0 + e^{i(ph+lm)} cos(th/2)*a1
__global__ void prep_gates_kernel(const float* __restrict__ w, int w_elems) {
    int e = threadIdx.x;
    if (e >= NGATES) return;
    int l = (NLAYERS - 1) - e / NQ;     // matches plan emission order
    int q = (NQ - 1) - e % NQ;
    int base = (l * NQ + q) * 3;
    float th = 0.f, ph = 0.f, lm = 0.f;
    if (base + 2 < w_elems) { th = w[base]; ph = w[base + 1]; lm = w[base + 2]; }
    float c, s;
    sincosf(0.5f * th, &s, &c);
    float cp, sp;   sincosf(ph, &sp, &cp);
    float cl, sl;   sincosf(lm, &sl, &cl);
    float cpl, spl; sincosf(ph + lm, &spl, &cpl);
    g_gates[e][0] = make_float2(c, 0.0f);
    g_gates[e][1] = make_float2(cp * s, sp * s);
    g_gates[e][2] = make_float2(-cl * s, -sl * s);
    g_gates[e][3] = make_float2(cpl * c, spl * c);
}

template <int OUT_MODE>   // 0 = real-only float, 1 = interleaved float2
__global__ __launch_bounds__(BLOCK)
void sim_kernel(const float* __restrict__ x, int x_elems,
                void* __restrict__ outv, int out_size, Plan plan) {
    __shared__ float2 st[NST];
    __shared__ float2 gg[NGATES][4];

    const int sid = blockIdx.x;
    const int tid = threadIdx.x;

    const long long ibase = (long long)sid * NST;
    for (int i = tid; i < NST; i += BLOCK) {
        long long gi = ibase + i;
        float re = (gi < x_elems) ? x[gi] : 0.0f;
        st[i] = make_float2(re, 0.0f);
    }
    for (int i = tid; i < NGATES * 4; i += BLOCK)
        ((float2*)gg)[i] = ((const float2*)g_gates)[i];
    __syncthreads();

    #pragma unroll 1
    for (int g = 0; g < NGATES; g++) {
        const unsigned m  = plan.m[g];
        const unsigned s  = plan.s[g];
        const int      hb = plan.hb[g];
        const float2 c00 = gg[g][0], c01 = gg[g][1];
        const float2 c10 = gg[g][2], c11 = gg[g][3];
        const unsigned lowmask = (1u << hb) - 1u;

        #pragma unroll
        for (int k = 0; k < 2; k++) {
            unsigned i = (unsigned)(tid + k * BLOCK);           // 0..511
            unsigned p = ((i & ~lowmask) << 1) | (i & lowmask); // insert 0 at bit hb
            if (__popc(p & s) & 1) p ^= m;                      // role-0 slot
            unsigned p1 = p ^ m;
            float2 a0 = st[p];
            float2 a1 = st[p1];
            float2 n0, n1;
            n0.x = c00.x * a0.x - c00.y * a0.y + c01.x * a1.x - c01.y * a1.y;
            n0.y = c00.x * a0.y + c00.y * a0.x + c01.x * a1.y + c01.y * a1.x;
            n1.x = c10.x * a0.x - c10.y * a0.y + c11.x * a1.x - c11.y * a1.y;
            n1.y = c10.x * a0.y + c10.y * a0.x + c11.x * a1.y + c11.y * a1.x;
            st[p]  = n0;
            st[p1] = n1;
        }
        __syncthreads();
    }

    // out[j] = st[phi^-1(j)], phi^-1(j) = XOR of outcols[b] over set bits of j.
    for (int j = tid; j < NST; j += BLOCK) {
        unsigned p = 0;
        #pragma unroll
        for (int b = 0; b < NQ; b++)
            if ((j >> b) & 1) p ^= plan.outcols[b];
        long long oi = ibase + j;
        if (OUT_MODE == 0) {
            if (oi < out_size) ((float*)outv)[oi] = st[p].x;
        } else {
            if (2 * oi + 1 < out_size) ((float2*)outv)[oi] = st[p];
        }
    }
}

extern "C" void kernel_launch(void* const* d_in, const int* in_sizes, int n_in,
                              void* d_out, int out_size) {
    // Identify inputs by element count (robust to metadata ordering):
    // x_freq = 128*16*32*32 = 2,097,152 ; weights = 5*10*3 = 150.
    const float* x_freq  = nullptr;  int x_elems = 0;
    const float* weights = nullptr;  int w_elems = 0;
    for (int i = 0; i < n_in; i++) {
        if (in_sizes[i] >= NSTATES * NST && !x_freq) {
            x_freq = (const float*)d_in[i]; x_elems = in_sizes[i];
        } else if (in_sizes[i] == NLAYERS * NQ * 3 && !weights) {
            weights = (const float*)d_in[i]; w_elems = in_sizes[i];
        }
    }
    if (!x_freq || !weights) {
        int big = 0;
        for (int i = 1; i < n_in; i++) if (in_sizes[i] > in_sizes[big]) big = i;
        x_freq = (const float*)d_in[big]; x_elems = in_sizes[big];
        int sm = (big == 0 && n_in > 1) ? 1 : 0;
        weights = (const float*)d_in[sm]; w_elems = in_sizes[sm];
    }

    prep_gates_kernel<<<1, 64>>>(weights, w_elems);

    // out_size == 2M  -> real float32 output (real parts only).
    // out_size >= 4M  -> float32 view of complex64, interleaved re/im.
    if (out_size <= NSTATES * NST)
        sim_kernel<0><<<NSTATES, BLOCK>>>(x_freq, x_elems, d_out, out_size, PLAN);
    else
        sim_kernel<1><<<NSTATES, BLOCK>>>(x_freq, x_elems, d_out, out_size, PLAN);
}

// round 6
// speedup vs baseline: 1.1238x; 1.1238x over previous
#include <cuda_runtime.h>
#include <cuda_bf16.h>

// Quantum circuit: N_QUBITS=10 (N=1024), N_LAYERS=5, out = U @ state per (b,c).
// Register-resident simulation. One WARP per state: 32 float2 regs/lane.
// All 50 gates fully unrolled at compile time (Plan is constexpr): register
// part of each pair mask -> static register pairing, lane part -> warp
// shuffles. No shared memory, no barriers in the hot loop.
//
// ENDIANNESS: qubit q (axis q+1) is bit (NQ-1-q) of the flattened index.

#define NQ      10
#define NST     1024
#define NLAYERS 5
#define NGATES  (NLAYERS * NQ)
#define NSTATES 2048          // 128 * 16
#define LANES   32

struct Plan {
    unsigned m[NGATES];       // pair mask in array space (phi^-1 e_b)
    unsigned s[NGATES];       // parity mask              (row b of phi)
    unsigned jreg[32];        // output index contribution of register bits
    unsigned rlow[NQ];        // rows_final[b] & 31  (lane contribution)
};

__host__ __device__ constexpr int highest_bit(unsigned v) {
    int h = 0; while (v >>= 1) h++; return h;
}
__host__ __device__ constexpr int parity10(unsigned x) {
    int p = 0;
    for (int k = 0; k < NQ; k++) p ^= (int)((x >> k) & 1u);
    return p;
}

// Vector-application order (reverse of U's build order):
//   for l = L-1..0: CNOTs q=9..0 (control q -> target (q+1)%10), then u3^T q=9..0.
// Invariant A[p] = v[phi(p)]; CNOT X: phi' = X*phi (rows), phi'^-1 = phi^-1*X (cols).
__host__ __device__ constexpr Plan make_plan() {
    Plan P{};
    unsigned rows[NQ] = {}, cols[NQ] = {};
    for (int r = 0; r < NQ; r++) { rows[r] = 1u << r; cols[r] = 1u << r; }
    int g = 0;
    for (int l = NLAYERS - 1; l >= 0; l--) {
        for (int q = NQ - 1; q >= 0; q--) {
            int c = NQ - 1 - q;                 // control bit
            int t = NQ - 1 - ((q + 1) % NQ);    // target bit
            rows[t] ^= rows[c];
            cols[c] ^= cols[t];
        }
        for (int q = NQ - 1; q >= 0; q--) {
            int b = NQ - 1 - q;
            P.m[g] = cols[b];
            P.s[g] = rows[b];
            g++;
        }
    }
    // Final map: out index j = phi(p); bit b of j = parity(p & rows[b]).
    for (int r = 0; r < 32; r++) {
        unsigned j = 0;
        for (int b = 0; b < NQ; b++)
            j ^= (unsigned)parity10(((unsigned)r << 5) & rows[b]) << b;
        P.jreg[r] = j;
    }
    for (int b = 0; b < NQ; b++) P.rlow[b] = rows[b] & 31u;
    return P;
}

static constexpr Plan PLAN = make_plan();

__device__ float2 g_gates[NGATES][4];   // scratch (no allocation)

// Coefficients for applying G^T to the vector:
//   n0 =  cos(th/2)*a0          + e^{i ph} sin(th/2)*a1
//   n1 = -e^{i lm} sin(th/2)*a0 + e^{i(ph+lm)} cos(th/2)*a1
__global__ void prep_gates_kernel(const float* __restrict__ w, int w_elems) {
    int e = threadIdx.x;
    if (e >= NGATES) return;
    int l = (NLAYERS - 1) - e / NQ;     // matches plan emission order
    int q = (NQ - 1) - e % NQ;
    int base = (l * NQ + q) * 3;
    float th = 0.f, ph = 0.f, lm = 0.f;
    if (base + 2 < w_elems) { th = w[base]; ph = w[base + 1]; lm = w[base + 2]; }
    float c, s;
    sincosf(0.5f * th, &s, &c);
    float cp, sp;   sincosf(ph, &sp, &cp);
    float cl, sl;   sincosf(lm, &sl, &cl);
    float cpl, spl; sincosf(ph + lm, &spl, &cpl);
    g_gates[e][0] = make_float2(c, 0.0f);
    g_gates[e][1] = make_float2(cp * s, sp * s);
    g_gates[e][2] = make_float2(-cl * s, -sl * s);
    g_gates[e][3] = make_float2(cpl * c, spl * c);
}

__device__ __forceinline__ float2 bf(float2 a, float2 w, float2 cs, float2 cp) {
    float2 n;
    n.x = cs.x * a.x - cs.y * a.y + cp.x * w.x - cp.y * w.y;
    n.y = cs.x * a.y + cs.y * a.x + cp.x * w.y + cp.y * w.x;
    return n;
}

// All masks arrive as integer template parameters (no PLAN access in device code).
template <int G, unsigned M, unsigned S>
__device__ __forceinline__ void apply_gate(float2 (&v)[32], int lane) {
    constexpr unsigned ML = M & 31u;        // lane part of pair mask
    constexpr unsigned MR = M >> 5;         // register part of pair mask
    constexpr unsigned SL = S & 31u;        // lane part of parity mask
    constexpr unsigned SR = S >> 5;         // register part of parity mask

    const float2 c00 = __ldg(&g_gates[G][0]);
    const float2 c01 = __ldg(&g_gates[G][1]);
    const float2 c10 = __ldg(&g_gates[G][2]);
    const float2 c11 = __ldg(&g_gates[G][3]);

    // role(p) = parity(p & S); split into reg-parity (compile-time) ^ lane-parity.
    const bool lp = (__popc(lane & (int)SL) & 1) != 0;
    const float2 cs0 = lp ? c11 : c00, cp0 = lp ? c10 : c01;  // reg-parity 0
    const float2 cs1 = lp ? c00 : c11, cp1 = lp ? c01 : c10;  // reg-parity 1

    if constexpr (MR == 0) {
        // partner in same register, other lane
        #pragma unroll
        for (int r = 0; r < 32; r++) {
            float wx = __shfl_xor_sync(0xffffffffu, v[r].x, (int)ML);
            float wy = __shfl_xor_sync(0xffffffffu, v[r].y, (int)ML);
            const bool rp = (__popc((unsigned)r & SR) & 1) != 0;
            v[r] = bf(v[r], make_float2(wx, wy), rp ? cs1 : cs0, rp ? cp1 : cp0);
        }
    } else {
        constexpr int HB = highest_bit(MR);
        #pragma unroll
        for (int r = 0; r < 32; r++) {
            if ((r >> HB) & 1) continue;          // each pair handled once
            const int r2 = r ^ (int)MR;
            float2 w, u;
            if constexpr (ML != 0) {
                w.x = __shfl_xor_sync(0xffffffffu, v[r2].x, (int)ML);
                w.y = __shfl_xor_sync(0xffffffffu, v[r2].y, (int)ML);
                u.x = __shfl_xor_sync(0xffffffffu, v[r].x,  (int)ML);
                u.y = __shfl_xor_sync(0xffffffffu, v[r].y,  (int)ML);
            } else {
                w = v[r2];
                u = v[r];
            }
            const float2 a = v[r], b = v[r2];
            const bool rpA = (__popc((unsigned)r  & SR) & 1) != 0;
            const bool rpB = (__popc((unsigned)r2 & SR) & 1) != 0;
            v[r]  = bf(a, w, rpA ? cs1 : cs0, rpA ? cp1 : cp0);
            v[r2] = bf(b, u, rpB ? cs1 : cs0, rpB ? cp1 : cp0);
        }
    }
}

template <int G>
struct GateSeq {
    static __device__ __forceinline__ void run(float2 (&v)[32], int lane) {
        apply_gate<G, PLAN.m[G], PLAN.s[G]>(v, lane);
        GateSeq<G + 1>::run(v, lane);
    }
};
template <>
struct GateSeq<NGATES> {
    static __device__ __forceinline__ void run(float2 (&)[32], int) {}
};

struct OutMap {
    unsigned short jreg[32];
    unsigned char  rlow[NQ];
};

template <int OUT_MODE>   // 0 = real-only float, 1 = interleaved float2
__global__ __launch_bounds__(32)
void sim_kernel(const float* __restrict__ x, int x_elems,
                void* __restrict__ outv, int out_size, OutMap om) {
    const int lane = threadIdx.x;
    const long long base = (long long)blockIdx.x * NST;

    float2 v[32];
    #pragma unroll
    for (int r = 0; r < 32; r++) {
        long long gi = base + (r << 5) + lane;            // coalesced
        v[r] = make_float2(gi < x_elems ? x[gi] : 0.0f, 0.0f);
    }

    GateSeq<0>::run(v, lane);

    // out[phi(p)] = v-slot p ;  phi(p) = jreg(reg) ^ jlane(lane)
    unsigned jl = 0;
    #pragma unroll
    for (int b = 0; b < NQ; b++)
        jl ^= (unsigned)((__popc(lane & (int)om.rlow[b]) & 1) << b);

    #pragma unroll
    for (int r = 0; r < 32; r++) {
        unsigned j = (unsigned)om.jreg[r] ^ jl;
        long long oi = base + j;
        if (OUT_MODE == 0) {
            if (oi < out_size) ((float*)outv)[oi] = v[r].x;
        } else {
            if (2 * oi + 1 < out_size) ((float2*)outv)[oi] = v[r];
        }
    }
}

extern "C" void kernel_launch(void* const* d_in, const int* in_sizes, int n_in,
                              void* d_out, int out_size) {
    // Identify inputs by element count (robust to metadata ordering).
    const float* x_freq  = nullptr;  int x_elems = 0;
    const float* weights = nullptr;  int w_elems = 0;
    for (int i = 0; i < n_in; i++) {
        if (in_sizes[i] >= NSTATES * NST && !x_freq) {
            x_freq = (const float*)d_in[i]; x_elems = in_sizes[i];
        } else if (in_sizes[i] == NLAYERS * NQ * 3 && !weights) {
            weights = (const float*)d_in[i]; w_elems = in_sizes[i];
        }
    }
    if (!x_freq || !weights) {
        int big = 0;
        for (int i = 1; i < n_in; i++) if (in_sizes[i] > in_sizes[big]) big = i;
        x_freq = (const float*)d_in[big]; x_elems = in_sizes[big];
        int sm = (big == 0 && n_in > 1) ? 1 : 0;
        weights = (const float*)d_in[sm]; w_elems = in_sizes[sm];
    }

    prep_gates_kernel<<<1, 64>>>(weights, w_elems);

    OutMap om;
    for (int r = 0; r < 32; r++) om.jreg[r] = (unsigned short)PLAN.jreg[r];
    for (int b = 0; b < NQ; b++) om.rlow[b] = (unsigned char)PLAN.rlow[b];

    // out_size == 2M -> real float32 output; >= 4M -> interleaved complex64.
    if (out_size <= NSTATES * NST)
        sim_kernel<0><<<NSTATES, LANES>>>(x_freq, x_elems, d_out, out_size, om);
    else
        sim_kernel<1><<<NSTATES, LANES>>>(x_freq, x_elems, d_out, out_size, om);
}

// round 7
// speedup vs baseline: 1.4264x; 1.2693x over previous
#include <cuda_runtime.h>
#include <cuda_bf16.h>

// Quantum circuit: N_QUBITS=10 (N=1024), N_LAYERS=5, out = U @ state per (b,c).
// R7: register-resident sim, 2 WARPS per state (CTA=64): 16 float2 regs/lane.
// Physical index p: bits 0-4 = lane, 5-8 = register, 9 = warp.
// All 50 gates unrolled; GF(2) CNOT-folded masks are immediates. Gates whose
// mask has the warp bit exchange via an 8KB smem buffer (+2 barriers); a
// compile-time basis transform B on reg/warp bits minimizes how many.
//
// ENDIANNESS: qubit q (axis q+1) is bit (NQ-1-q) of the flattened index.

#define NQ      10
#define NST     1024
#define NLAYERS 5
#define NGATES  (NLAYERS * NQ)
#define NSTATES 2048          // 128 * 16
#define BLOCK   64
#define REGS    16

__host__ __device__ constexpr int highest_bit(unsigned v) {
    int h = 0; while (v >>= 1) h++; return h;
}
__host__ __device__ constexpr int parity10(unsigned x) {
    int p = 0;
    for (int k = 0; k < NQ; k++) p ^= (int)((x >> k) & 1u);
    return p;
}

struct M5 { unsigned r[5]; };   // 5x5 GF(2) matrix as row masks

__host__ __device__ constexpr M5 gf2inv5(M5 A) {
    unsigned a[5] = {}, b[5] = {};
    for (int i = 0; i < 5; i++) { a[i] = A.r[i]; b[i] = 1u << i; }
    for (int c = 0; c < 5; c++) {
        int p = -1;
        for (int i = c; i < 5; i++) if ((a[i] >> c) & 1u) { p = i; break; }
        unsigned ta = a[c]; a[c] = a[p]; a[p] = ta;
        unsigned tb = b[c]; b[c] = b[p]; b[p] = tb;
        for (int i = 0; i < 5; i++)
            if (i != c && ((a[i] >> c) & 1u)) { a[i] ^= a[c]; b[i] ^= b[c]; }
    }
    M5 R{};
    for (int i = 0; i < 5; i++) R.r[i] = b[i];
    return R;
}

struct Plan {
    unsigned m[NGATES];      // physical pair mask
    unsigned s[NGATES];      // physical parity mask
    unsigned lrow[32];       // load: v-row per preg = (warp<<4)|reg
    unsigned jreg[32];       // store: index contribution of (warp,reg)
    unsigned rlow[NQ];       // store: rows_final[b] & 31 (lane contribution)
};

// CNOT/gate recursion in vector-application order (reverse of build order),
// starting from phi = T (rows/cols pre-initialized).
__host__ __device__ constexpr void run_circuit(unsigned (&rows)[NQ], unsigned (&cols)[NQ],
                                               unsigned* m_out, unsigned* s_out) {
    int g = 0;
    for (int l = NLAYERS - 1; l >= 0; l--) {
        for (int q = NQ - 1; q >= 0; q--) {
            int c = NQ - 1 - q;                 // control bit
            int t = NQ - 1 - ((q + 1) % NQ);    // target bit
            rows[t] ^= rows[c];
            cols[c] ^= cols[t];
        }
        for (int q = NQ - 1; q >= 0; q--) {
            int b = NQ - 1 - q;
            if (m_out) m_out[g] = cols[b];
            if (s_out) s_out[g] = rows[b];
            g++;
        }
    }
}

__host__ __device__ constexpr Plan make_plan() {
    // Pass 1: identity basis -> raw masks, to pick the basis B.
    unsigned m0[NGATES] = {};
    {
        unsigned rows[NQ] = {}, cols[NQ] = {};
        for (int r = 0; r < NQ; r++) { rows[r] = 1u << r; cols[r] = 1u << r; }
        run_circuit(rows, cols, m0, nullptr);
    }
    // Choose row4 of Binv minimizing # gates with warp bit set in transformed mask.
    unsigned rbest = 1; int best = NGATES + 1;
    for (unsigned r = 1; r < 32; r++) {
        int cnt = 0;
        for (int g = 0; g < NGATES; g++)
            cnt += parity10(((m0[g] >> 5) & 31u) & r);
        if (cnt < best) { best = cnt; rbest = r; }
    }
    // Complete Binv to full rank (row4 = rbest; rows0-3 greedy independent).
    M5 Binv{};
    {
        unsigned chosen[5] = {rbest, 0, 0, 0, 0};
        int nch = 1;
        for (unsigned cand = 1; cand < 32 && nch < 5; cand++) {
            // independence test via elimination against chosen set
            unsigned v = cand;
            unsigned basis[5] = {};
            int nb = 0;
            for (int i = 0; i < nch; i++) basis[nb++] = chosen[i];
            // reduce v
            for (int bit = 4; bit >= 0; bit--) {
                for (int i = 0; i < nb; i++) {
                    if (highest_bit(basis[i]) == bit && ((v >> bit) & 1u) && basis[i])
                        v ^= basis[i];
                }
            }
            // crude full reduction: repeat elimination
            for (int pass = 0; pass < 5; pass++)
                for (int i = 0; i < nb; i++)
                    if (basis[i] && ((v >> highest_bit(basis[i])) & 1u)) v ^= basis[i];
            if (v != 0) chosen[nch++] = cand;
        }
        Binv.r[4] = chosen[0];
        for (int i = 0; i < 4; i++) Binv.r[i] = chosen[1 + i];
    }
    M5 B = gf2inv5(Binv);

    Plan P{};
    // Pass 2: full plan with phi initialized to T = diag(I5, B).
    unsigned rows[NQ] = {}, cols[NQ] = {};
    for (int b = 0; b < 5; b++) { rows[b] = 1u << b; cols[b] = 1u << b; }
    for (int i = 0; i < 5; i++) {
        rows[5 + i] = B.r[i] << 5;
        unsigned colv = 0;                       // column i of Binv
        for (int j = 0; j < 5; j++) colv |= ((Binv.r[j] >> i) & 1u) << j;
        cols[5 + i] = colv << 5;
    }
    run_circuit(rows, cols, P.m, P.s);

    // Load map: v-row for preg = B(preg).
    for (unsigned preg = 0; preg < 32; preg++) {
        unsigned R = 0;
        for (int i = 0; i < 5; i++) R |= (unsigned)parity10(preg & B.r[i]) << i;
        P.lrow[preg] = R;
    }
    // Store map: j = phi_final(p); bit b = parity(p & rows[b]).
    for (unsigned preg = 0; preg < 32; preg++) {
        unsigned j = 0;
        for (int b = 0; b < NQ; b++)
            j ^= (unsigned)parity10((preg << 5) & rows[b]) << b;
        P.jreg[preg] = j;
    }
    for (int b = 0; b < NQ; b++) P.rlow[b] = rows[b] & 31u;
    return P;
}

static constexpr Plan PLAN = make_plan();

__device__ float2 g_gates[NGATES][4];   // scratch (no allocation)

// Coefficients for applying G^T to the vector:
//   n0 =  cos(th/2)*a0          + e^{i ph} sin(th/2)*a1
//   n1 = -e^{i lm} sin(th/2)*a0 + e^{i(ph+lm)} cos(th/2)*a1
__global__ void prep_gates_kernel(const float* __restrict__ w, int w_elems) {
    int e = threadIdx.x;
    if (e >= NGATES) return;
    int l = (NLAYERS - 1) - e / NQ;     // matches plan emission order
    int q = (NQ - 1) - e % NQ;
    int base = (l * NQ + q) * 3;
    float th = 0.f, ph = 0.f, lm = 0.f;
    if (base + 2 < w_elems) { th = w[base]; ph = w[base + 1]; lm = w[base + 2]; }
    float c, s;
    sincosf(0.5f * th, &s, &c);
    float cp, sp;   sincosf(ph, &sp, &cp);
    float cl, sl;   sincosf(lm, &sl, &cl);
    float cpl, spl; sincosf(ph + lm, &spl, &cpl);
    g_gates[e][0] = make_float2(c, 0.0f);
    g_gates[e][1] = make_float2(cp * s, sp * s);
    g_gates[e][2] = make_float2(-cl * s, -sl * s);
    g_gates[e][3] = make_float2(cpl * c, spl * c);
}

__device__ __forceinline__ float2 bf(float2 a, float2 w, float2 cs, float2 cp) {
    float2 n;
    n.x = cs.x * a.x - cs.y * a.y + cp.x * w.x - cp.y * w.y;
    n.y = cs.x * a.y + cs.y * a.x + cp.x * w.y + cp.y * w.x;
    return n;
}

// Masks as template parameters (no PLAN access inside device code paths).
template <int G, unsigned M, unsigned S>
__device__ __forceinline__ void apply_gate(float2 (&v)[REGS], int lane, int wid,
                                           float2 (*sm)[BLOCK]) {
    constexpr unsigned ML = M & 31u;          // lane part
    constexpr unsigned MR = (M >> 5) & 15u;   // register part
    constexpr unsigned MW = M >> 9;           // warp part
    constexpr unsigned SL = S & 31u;
    constexpr unsigned SR = (S >> 5) & 15u;
    constexpr unsigned SW = S >> 9;

    const float2 c00 = __ldg(&g_gates[G][0]);
    const float2 c01 = __ldg(&g_gates[G][1]);
    const float2 c10 = __ldg(&g_gates[G][2]);
    const float2 c11 = __ldg(&g_gates[G][3]);

    // role(p) = parity(p & S) = CT reg-parity ^ runtime (lane,warp)-parity.
    const bool lw = ((__popc(lane & (int)SL) ^ (wid & (int)SW)) & 1) != 0;
    const float2 cs0 = lw ? c11 : c00, cp0 = lw ? c10 : c01;  // reg-parity 0
    const float2 cs1 = lw ? c00 : c11, cp1 = lw ? c01 : c10;  // reg-parity 1

    if constexpr (MW != 0) {
        // Cross-warp gate: exchange via shared memory.
        const int tid = (wid << 5) | lane;
        __syncthreads();                       // buffer free from previous use
        #pragma unroll
        for (int r = 0; r < REGS; r++) sm[r][tid] = v[r];
        __syncthreads();
        const int ptid = tid ^ 32 ^ (int)ML;   // partner thread (other warp)
        #pragma unroll
        for (int r = 0; r < REGS; r++) {
            float2 w = sm[r ^ (int)MR][ptid];
            const bool rp = (__popc((unsigned)r & SR) & 1) != 0;
            v[r] = bf(v[r], w, rp ? cs1 : cs0, rp ? cp1 : cp0);
        }
    } else if constexpr (MR == 0) {
        // partner in same register, other lane
        #pragma unroll
        for (int r = 0; r < REGS; r++) {
            float wx = __shfl_xor_sync(0xffffffffu, v[r].x, (int)ML);
            float wy = __shfl_xor_sync(0xffffffffu, v[r].y, (int)ML);
            const bool rp = (__popc((unsigned)r & SR) & 1) != 0;
            v[r] = bf(v[r], make_float2(wx, wy), rp ? cs1 : cs0, rp ? cp1 : cp0);
        }
    } else {
        constexpr int HB = highest_bit(MR);
        #pragma unroll
        for (int r = 0; r < REGS; r++) {
            if ((r >> HB) & 1) continue;          // each pair handled once
            const int r2 = r ^ (int)MR;
            float2 w, u;
            if constexpr (ML != 0) {
                w.x = __shfl_xor_sync(0xffffffffu, v[r2].x, (int)ML);
                w.y = __shfl_xor_sync(0xffffffffu, v[r2].y, (int)ML);
                u.x = __shfl_xor_sync(0xffffffffu, v[r].x,  (int)ML);
                u.y = __shfl_xor_sync(0xffffffffu, v[r].y,  (int)ML);
            } else {
                w = v[r2];
                u = v[r];
            }
            const float2 a = v[r], b = v[r2];
            const bool rpA = (__popc((unsigned)r  & SR) & 1) != 0;
            const bool rpB = (__popc((unsigned)r2 & SR) & 1) != 0;
            v[r]  = bf(a, w, rpA ? cs1 : cs0, rpA ? cp1 : cp0);
            v[r2] = bf(b, u, rpB ? cs1 : cs0, rpB ? cp1 : cp0);
        }
    }
}

template <int G>
struct GateSeq {
    static __device__ __forceinline__ void run(float2 (&v)[REGS], int lane, int wid,
                                               float2 (*sm)[BLOCK]) {
        apply_gate<G, PLAN.m[G], PLAN.s[G]>(v, lane, wid, sm);
        GateSeq<G + 1>::run(v, lane, wid, sm);
    }
};
template <>
struct GateSeq<NGATES> {
    static __device__ __forceinline__ void run(float2 (&)[REGS], int, int,
                                               float2 (*)[BLOCK]) {}
};

struct PParam {
    unsigned short lrow[32];
    unsigned short jreg[32];
    unsigned char  rlow[NQ];
};

template <int OUT_MODE>   // 0 = real-only float, 1 = interleaved float2
__global__ __launch_bounds__(BLOCK)
void sim_kernel(const float* __restrict__ x, int x_elems,
                void* __restrict__ outv, int out_size, PParam pp) {
    __shared__ float2 sm[REGS][BLOCK];

    const int tid  = threadIdx.x;
    const int lane = tid & 31;
    const int wid  = tid >> 5;
    const long long base = (long long)blockIdx.x * NST;

    float2 v[REGS];
    #pragma unroll
    for (int r = 0; r < REGS; r++) {
        int row = pp.lrow[(wid << 4) | r];
        long long gi = base + (row << 5) + lane;          // coalesced per warp
        v[r] = make_float2(gi < x_elems ? x[gi] : 0.0f, 0.0f);
    }

    GateSeq<0>::run(v, lane, wid, sm);

    // out[phi(p)] = slot p ;  phi(p) = jreg(warp,reg) ^ jlane(lane)
    unsigned jl = 0;
    #pragma unroll
    for (int b = 0; b < NQ; b++)
        jl ^= (unsigned)((__popc(lane & (int)pp.rlow[b]) & 1) << b);

    #pragma unroll
    for (int r = 0; r < REGS; r++) {
        unsigned j = (unsigned)pp.jreg[(wid << 4) | r] ^ jl;
        long long oi = base + j;
        if (OUT_MODE == 0) {
            if (oi < out_size) ((float*)outv)[oi] = v[r].x;
        } else {
            if (2 * oi + 1 < out_size) ((float2*)outv)[oi] = v[r];
        }
    }
}

extern "C" void kernel_launch(void* const* d_in, const int* in_sizes, int n_in,
                              void* d_out, int out_size) {
    // Identify inputs by element count (robust to metadata ordering).
    const float* x_freq  = nullptr;  int x_elems = 0;
    const float* weights = nullptr;  int w_elems = 0;
    for (int i = 0; i < n_in; i++) {
        if (in_sizes[i] >= NSTATES * NST && !x_freq) {
            x_freq = (const float*)d_in[i]; x_elems = in_sizes[i];
        } else if (in_sizes[i] == NLAYERS * NQ * 3 && !weights) {
            weights = (const float*)d_in[i]; w_elems = in_sizes[i];
        }
    }
    if (!x_freq || !weights) {
        int big = 0;
        for (int i = 1; i < n_in; i++) if (in_sizes[i] > in_sizes[big]) big = i;
        x_freq = (const float*)d_in[big]; x_elems = in_sizes[big];
        int sm = (big == 0 && n_in > 1) ? 1 : 0;
        weights = (const float*)d_in[sm]; w_elems = in_sizes[sm];
    }

    prep_gates_kernel<<<1, 64>>>(weights, w_elems);

    PParam pp;
    for (int i = 0; i < 32; i++) pp.lrow[i] = (unsigned short)PLAN.lrow[i];
    for (int i = 0; i < 32; i++) pp.jreg[i] = (unsigned short)PLAN.jreg[i];
    for (int b = 0; b < NQ; b++) pp.rlow[b] = (unsigned char)PLAN.rlow[b];

    // out_size == 2M -> real float32 output; >= 4M -> interleaved complex64.
    if (out_size <= NSTATES * NST)
        sim_kernel<0><<<NSTATES, BLOCK>>>(x_freq, x_elems, d_out, out_size, pp);
    else
        sim_kernel<1><<<NSTATES, BLOCK>>>(x_freq, x_elems, d_out, out_size, pp);
}